// round 1
// baseline (speedup 1.0000x reference)
#include <cuda_runtime.h>
#include <cuda_fp16.h>

#define EPSF 1e-8f
#define COLS 8192
#define BS 64
#define NB 128          // blocks per row
#define NCELL 256       // LUT cells over x_norm in [-1,1)
#define NTHREADS 256

// Each CTA processes one row (8192 floats).
// Warp w owns quant-blocks [16w, 16w+16). Iteration i: lanes 0-15 cover
// quant-block 16w+2i (float4 each), lanes 16-31 cover 16w+2i+1 -> each
// warp-iteration touches 512 contiguous bytes (fully coalesced).
__global__ __launch_bounds__(NTHREADS, 1)
void nf4_kernel(const float* __restrict__ x, float* __restrict__ out)
{
    __shared__ float4 lut[NCELL + 1];   // {midpoint_cell, t_lo, t_hi, pad}
    __shared__ float4 qc[NB];           // {s1, s2, a, b} per quant-block
    __shared__ float scale_s[NB];
    __shared__ float bmin_s[NB];
    __shared__ float t_s[16];
    __shared__ float m_s[15];           // midpoints, in cell coordinates
    __shared__ float sm_smin, sm_smax;

    const int tid  = threadIdx.x;
    const int lane = tid & 31;
    const int warp = tid >> 5;
    const long long row_base = (long long)blockIdx.x * COLS;

    // ---- phase 0: NF4 table (ndtri at midpoints, normalized, fp16-rounded) ----
    if (tid < 16) {
        // ndtri(p) = sqrt(2)*erfinv(2p-1); the sqrt(2) cancels in the
        // max-abs normalization.
        float p   = (2.0f * ((float)tid + 0.5f)) / 16.0f - 1.0f;
        float q   = erfinvf(p);
        float q0  = erfinvf(2.0f * 0.5f  / 16.0f - 1.0f);
        float q15 = erfinvf(2.0f * 15.5f / 16.0f - 1.0f);
        float qmax = fmaxf(fabsf(q0), fabsf(q15));
        t_s[tid] = __half2float(__float2half(q / qmax));
    }
    __syncthreads();
    if (tid < 15) {
        // decision boundary between level tid and tid+1, mapped to cell coords:
        // cell(x_norm) = (x_norm + 1) * 128
        m_s[tid] = ((t_s[tid] + t_s[tid + 1]) * 0.5f + 1.0f) * 128.0f;
    }
    __syncthreads();

    // ---- phase 0b: build range LUT. Min midpoint gap ~10.8 cells, so each
    // cell straddles at most one boundary. Strict '>' matches argmin's
    // first-index tie rule (tie -> lower level).
    for (int c = tid; c <= NCELL; c += NTHREADS) {
        int jlo = 0, jhi = 0;
        float fc = (float)c;
        #pragma unroll
        for (int k = 0; k < 15; k++) {
            jlo += (m_s[k] < fc)        ? 1 : 0;
            jhi += (m_s[k] < fc + 1.0f) ? 1 : 0;
        }
        float4 e;
        if (jhi > jlo) { e.x = m_s[jlo]; e.y = t_s[jlo]; e.z = t_s[jlo + 1]; }
        else           { e.x = -1e30f;   e.y = t_s[jlo]; e.z = t_s[jlo];     }
        e.w = 0.0f;
        lut[c] = e;
    }

    // ---- phase 1: load row into registers + per-block min/max ----
    float4 v[8];
    const int qb_base = warp * 16;
    #pragma unroll
    for (int i = 0; i < 8; i++) {
        int e = (qb_base + 2 * i) * BS + lane * 4;
        v[i] = *reinterpret_cast<const float4*>(x + row_base + e);
    }
    #pragma unroll
    for (int i = 0; i < 8; i++) {
        float mn = fminf(fminf(v[i].x, v[i].y), fminf(v[i].z, v[i].w));
        float mx = fmaxf(fmaxf(v[i].x, v[i].y), fmaxf(v[i].z, v[i].w));
        // butterfly over each 16-lane half (two quant-blocks reduced at once)
        #pragma unroll
        for (int o = 8; o >= 1; o >>= 1) {
            mn = fminf(mn, __shfl_xor_sync(0xffffffffu, mn, o));
            mx = fmaxf(mx, __shfl_xor_sync(0xffffffffu, mx, o));
        }
        if ((lane & 15) == 0) {
            int qb = qb_base + 2 * i + (lane >> 4);
            bmin_s[qb]  = mn;
            scale_s[qb] = mx - mn;   // exact: same fp32 subtract as reference
        }
    }
    __syncthreads();

    // ---- phase 2: row-level min/max of the 128 block scales ----
    if (warp == 0) {
        float a0 = scale_s[lane];
        float a1 = scale_s[lane + 32];
        float a2 = scale_s[lane + 64];
        float a3 = scale_s[lane + 96];
        float mn = fminf(fminf(a0, a1), fminf(a2, a3));
        float mx = fmaxf(fmaxf(a0, a1), fmaxf(a2, a3));
        #pragma unroll
        for (int o = 16; o >= 1; o >>= 1) {
            mn = fminf(mn, __shfl_xor_sync(0xffffffffu, mn, o));
            mx = fmaxf(mx, __shfl_xor_sync(0xffffffffu, mx, o));
        }
        if (lane == 0) { sm_smin = mn; sm_smax = mx; }
    }
    __syncthreads();

    // ---- phase 3: per-block fused constants ----
    if (tid < NB) {
        float smin  = sm_smin, smax = sm_smax;
        float scale = scale_s[tid];
        float bmin  = bmin_s[tid];
        float d     = smax - smin;
        // double quantization of the scale (8-bit, round-half-even = rintf)
        float sq    = rintf((scale - smin) / (d + EPSF) * 255.0f);
        float srec  = smin + sq / 255.0f * d;
        // out = (t+1)/2 * srec + bmin  ==  t*a + b
        float a  = srec * 0.5f;
        float b  = a + bmin;
        // cell(x) = (x_norm+1)*128 = (x - bmin) * 256/(scale+eps) = x*s1 + s2
        float s1 = 256.0f / (scale + EPSF);
        float s2 = -bmin * s1;
        qc[tid] = make_float4(s1, s2, a, b);
    }
    __syncthreads();

    // ---- phase 4: quantize->dequantize from registers, store ----
    #pragma unroll
    for (int i = 0; i < 8; i++) {
        int qb = qb_base + 2 * i + (lane >> 4);
        float4 cst = qc[qb];
        float4 o;
        float* vi = reinterpret_cast<float*>(&v[i]);
        float* oo = reinterpret_cast<float*>(&o);
        #pragma unroll
        for (int j = 0; j < 4; j++) {
            float fcell = fmaf(vi[j], cst.x, cst.y);
            int ic = (int)fcell;            // trunc-to-zero clamps tiny negatives to 0
            float4 L = lut[ic];             // ic can reach 256 -> LUT has 257 entries
            float t = (fcell > L.x) ? L.z : L.y;
            oo[j] = fmaf(t, cst.z, cst.w);
        }
        int e = (qb_base + 2 * i) * BS + lane * 4;
        *reinterpret_cast<float4*>(out + row_base + e) = o;
    }
}

extern "C" void kernel_launch(void* const* d_in, const int* in_sizes, int n_in,
                              void* d_out, int out_size)
{
    const float* x = (const float*)d_in[0];
    float* out = (float*)d_out;
    int rows = in_sizes[0] / COLS;   // 2048
    nf4_kernel<<<rows, NTHREADS>>>(x, out);
}

// round 2
// speedup vs baseline: 1.0486x; 1.0486x over previous
#include <cuda_runtime.h>
#include <cuda_fp16.h>

#define EPSF 1e-8f
#define COLS 8192
#define BS 64
#define NB 128          // blocks per row
#define NCELL 256       // LUT cells over x_norm in [-1,1)
#define NTHREADS 256

// Each CTA processes one row (8192 floats).
// Warp w owns quant-blocks [16w, 16w+16). Iteration i: lanes 0-15 cover
// quant-block 16w+2i (float4 each), lanes 16-31 cover 16w+2i+1 -> each
// warp-iteration touches 512 contiguous bytes (fully coalesced).
//
// R2 change vs R1: x is NOT held in registers across the stats->quantize
// barrier; phase 4 re-reads it (L1-resident, same CTA/SM, L1D persists
// within a launch). Registers drop ~128 -> ~60, enabling 4 CTAs/SM.
__global__ __launch_bounds__(NTHREADS, 4)
void nf4_kernel(const float* __restrict__ x, float* __restrict__ out)
{
    __shared__ float4 lut[NCELL + 1];   // {midpoint_cell, t_lo, t_hi, pad}
    __shared__ float4 qc[NB];           // {s1, s2, a, b} per quant-block
    __shared__ float scale_s[NB];
    __shared__ float bmin_s[NB];
    __shared__ float t_s[16];
    __shared__ float m_s[15];           // midpoints, in cell coordinates
    __shared__ float sm_smin, sm_smax;

    const int tid  = threadIdx.x;
    const int lane = tid & 31;
    const int warp = tid >> 5;
    const long long row_base = (long long)blockIdx.x * COLS;

    // ---- phase 0: NF4 table (ndtri at midpoints, normalized, fp16-rounded) ----
    if (tid < 16) {
        // ndtri(p) = sqrt(2)*erfinv(2p-1); the sqrt(2) cancels in the
        // max-abs normalization.
        float p   = (2.0f * ((float)tid + 0.5f)) / 16.0f - 1.0f;
        float q   = erfinvf(p);
        float q0  = erfinvf(2.0f * 0.5f  / 16.0f - 1.0f);
        float q15 = erfinvf(2.0f * 15.5f / 16.0f - 1.0f);
        float qmax = fmaxf(fabsf(q0), fabsf(q15));
        t_s[tid] = __half2float(__float2half(q / qmax));
    }
    __syncthreads();
    if (tid < 15) {
        // decision boundary between level tid and tid+1, mapped to cell coords:
        // cell(x_norm) = (x_norm + 1) * 128
        m_s[tid] = ((t_s[tid] + t_s[tid + 1]) * 0.5f + 1.0f) * 128.0f;
    }
    __syncthreads();

    // ---- phase 0b: build range LUT. Min midpoint gap ~10.8 cells, so each
    // cell straddles at most one boundary. Strict '>' matches argmin's
    // first-index tie rule (tie -> lower level).
    for (int c = tid; c <= NCELL; c += NTHREADS) {
        int jlo = 0, jhi = 0;
        float fc = (float)c;
        #pragma unroll
        for (int k = 0; k < 15; k++) {
            jlo += (m_s[k] < fc)        ? 1 : 0;
            jhi += (m_s[k] < fc + 1.0f) ? 1 : 0;
        }
        float4 e;
        if (jhi > jlo) { e.x = m_s[jlo]; e.y = t_s[jlo]; e.z = t_s[jlo + 1]; }
        else           { e.x = -1e30f;   e.y = t_s[jlo]; e.z = t_s[jlo];     }
        e.w = 0.0f;
        lut[c] = e;
    }

    // ---- phase 1: stream row, per-block min/max (values NOT kept live) ----
    const int qb_base = warp * 16;
    #pragma unroll
    for (int i = 0; i < 8; i++) {
        int e = (qb_base + 2 * i) * BS + lane * 4;
        float4 v = *reinterpret_cast<const float4*>(x + row_base + e);
        float mn = fminf(fminf(v.x, v.y), fminf(v.z, v.w));
        float mx = fmaxf(fmaxf(v.x, v.y), fmaxf(v.z, v.w));
        // butterfly over each 16-lane half (two quant-blocks reduced at once)
        #pragma unroll
        for (int o = 8; o >= 1; o >>= 1) {
            mn = fminf(mn, __shfl_xor_sync(0xffffffffu, mn, o));
            mx = fmaxf(mx, __shfl_xor_sync(0xffffffffu, mx, o));
        }
        if ((lane & 15) == 0) {
            int qb = qb_base + 2 * i + (lane >> 4);
            bmin_s[qb]  = mn;
            scale_s[qb] = mx - mn;   // exact: same fp32 subtract as reference
        }
    }
    __syncthreads();

    // ---- phase 2: row-level min/max of the 128 block scales ----
    if (warp == 0) {
        float a0 = scale_s[lane];
        float a1 = scale_s[lane + 32];
        float a2 = scale_s[lane + 64];
        float a3 = scale_s[lane + 96];
        float mn = fminf(fminf(a0, a1), fminf(a2, a3));
        float mx = fmaxf(fmaxf(a0, a1), fmaxf(a2, a3));
        #pragma unroll
        for (int o = 16; o >= 1; o >>= 1) {
            mn = fminf(mn, __shfl_xor_sync(0xffffffffu, mn, o));
            mx = fmaxf(mx, __shfl_xor_sync(0xffffffffu, mx, o));
        }
        if (lane == 0) { sm_smin = mn; sm_smax = mx; }
    }
    __syncthreads();

    // ---- phase 3: per-block fused constants ----
    if (tid < NB) {
        float smin  = sm_smin, smax = sm_smax;
        float scale = scale_s[tid];
        float bmin  = bmin_s[tid];
        float d     = smax - smin;
        // double quantization of the scale (8-bit, round-half-even = rintf)
        float sq    = rintf((scale - smin) / (d + EPSF) * 255.0f);
        float srec  = smin + sq / 255.0f * d;
        // out = (t+1)/2 * srec + bmin  ==  t*a + b
        float a  = srec * 0.5f;
        float b  = a + bmin;
        // cell(x) = (x_norm+1)*128 = (x - bmin) * 256/(scale+eps) = x*s1 + s2
        float s1 = 256.0f / (scale + EPSF);
        float s2 = -bmin * s1;
        qc[tid] = make_float4(s1, s2, a, b);
    }
    __syncthreads();

    // ---- phase 4: re-read row (L1-hot), quantize->dequantize, store ----
    #pragma unroll
    for (int i = 0; i < 8; i++) {
        int qb = qb_base + 2 * i + (lane >> 4);
        int e  = (qb_base + 2 * i) * BS + lane * 4;
        float4 v = *reinterpret_cast<const float4*>(x + row_base + e);
        float4 cst = qc[qb];
        float4 o;
        float* vi = reinterpret_cast<float*>(&v);
        float* oo = reinterpret_cast<float*>(&o);
        #pragma unroll
        for (int j = 0; j < 4; j++) {
            float fcell = fmaf(vi[j], cst.x, cst.y);
            int ic = (int)fcell;            // trunc-to-zero clamps tiny negatives to 0
            float4 L = lut[ic];             // ic can reach 256 -> LUT has 257 entries
            float t = (fcell > L.x) ? L.z : L.y;
            oo[j] = fmaf(t, cst.z, cst.w);
        }
        *reinterpret_cast<float4*>(out + row_base + e) = o;
    }
}

extern "C" void kernel_launch(void* const* d_in, const int* in_sizes, int n_in,
                              void* d_out, int out_size)
{
    const float* x = (const float*)d_in[0];
    float* out = (float*)d_out;
    int rows = in_sizes[0] / COLS;   // 2048
    nf4_kernel<<<rows, NTHREADS>>>(x, out);
}

// round 4
// speedup vs baseline: 1.2310x; 1.1739x over previous
#include <cuda_runtime.h>
#include <cuda_fp16.h>
#include <cstdint>

#define EPSF 1e-8f
#define COLS 8192
#define BS 64
#define NB 128          // quant-blocks per row
#define NCELL 256       // LUT cells over x_norm in [-1,1)
#define NTHREADS 256

typedef unsigned int u32;

// One CTA per row (8192 floats). Warp w owns quant-blocks [16w, 16w+16).
// Iteration i: lanes 0-15 cover block 16w+2i, lanes 16-31 cover 16w+2i+1
// (float4 per lane; each warp-iter touches 512 contiguous bytes, coalesced).
//
// R3/R4 changes vs R2 (attack L1/MIO wavefronts, the measured binder):
//  - quantize fused into phase 1 (block stats are known in-registers right
//    after the butterfly); chosen fp16 table values stashed in 8 regs
//  - NO second read of x; phase 4 is pure register math + coalesced store
//  - LUT entries shrunk 16B -> 8B {midpoint_f32, half2(t_lo,t_hi)}
__global__ __launch_bounds__(NTHREADS, 4)
void nf4_kernel(const float* __restrict__ x, float* __restrict__ out)
{
    __shared__ float2 lut[NCELL + 1];   // {midpoint_cell, bits(half2(t_lo,t_hi))}
    __shared__ float2 qc[NB];           // {a, b} per quant-block
    __shared__ float scale_s[NB];
    __shared__ float bmin_s[NB];
    __shared__ float t_s[16];
    __shared__ float m_s[15];           // midpoints, in cell coordinates
    __shared__ float sm_smin, sm_smax;

    const int tid  = threadIdx.x;
    const int lane = tid & 31;
    const int warp = tid >> 5;
    const long long row_base = (long long)blockIdx.x * COLS;

    // ---- phase 0: NF4 table (ndtri at midpoints, normalized, fp16-rounded) ----
    if (tid < 16) {
        // ndtri(p) = sqrt(2)*erfinv(2p-1); sqrt(2) cancels in max-abs norm.
        float p   = (2.0f * ((float)tid + 0.5f)) / 16.0f - 1.0f;
        float q   = erfinvf(p);
        float q0  = erfinvf(2.0f * 0.5f  / 16.0f - 1.0f);
        float q15 = erfinvf(2.0f * 15.5f / 16.0f - 1.0f);
        float qmax = fmaxf(fabsf(q0), fabsf(q15));
        t_s[tid] = __half2float(__float2half(q / qmax));
    }
    __syncthreads();
    if (tid < 15) {
        // boundary between level tid and tid+1 in cell coords:
        // cell(x_norm) = (x_norm + 1) * 128
        m_s[tid] = ((t_s[tid] + t_s[tid + 1]) * 0.5f + 1.0f) * 128.0f;
    }
    __syncthreads();

    // ---- phase 0b: range LUT. Min midpoint gap ~10.8 cells -> each cell
    // straddles at most one boundary. Strict '>' matches argmin's
    // first-index tie rule (tie -> lower level).
    for (int c = tid; c <= NCELL; c += NTHREADS) {
        int jlo = 0, jhi = 0;
        float fc = (float)c;
        #pragma unroll
        for (int k = 0; k < 15; k++) {
            jlo += (m_s[k] < fc)        ? 1 : 0;
            jhi += (m_s[k] < fc + 1.0f) ? 1 : 0;
        }
        float2 e;
        __half2 tp;
        if (jhi > jlo) { e.x = m_s[jlo]; tp = __halves2half2(__float2half(t_s[jlo]), __float2half(t_s[jlo + 1])); }
        else           { e.x = -1e30f;   tp = __halves2half2(__float2half(t_s[jlo]), __float2half(t_s[jlo]));     }
        e.y = __uint_as_float(*reinterpret_cast<u32*>(&tp));
        lut[c] = e;
    }
    __syncthreads();   // LUT ready before phase-1 quantize

    // ---- phase 1: single pass: load, block min/max, quantize, stash fp16 ----
    const int qb_base = warp * 16;
    u32 stash[16];                      // 8 iters x 2 packed half2
    #pragma unroll
    for (int i = 0; i < 8; i++) {
        int e = (qb_base + 2 * i) * BS + lane * 4;
        float4 v = *reinterpret_cast<const float4*>(x + row_base + e);
        float mn = fminf(fminf(v.x, v.y), fminf(v.z, v.w));
        float mx = fmaxf(fmaxf(v.x, v.y), fmaxf(v.z, v.w));
        // butterfly over each 16-lane half (two quant-blocks at once)
        #pragma unroll
        for (int o = 8; o >= 1; o >>= 1) {
            mn = fminf(mn, __shfl_xor_sync(0xffffffffu, mn, o));
            mx = fmaxf(mx, __shfl_xor_sync(0xffffffffu, mx, o));
        }
        float scale = mx - mn;          // exact fp32 subtract, as reference
        if ((lane & 15) == 0) {
            int qb = qb_base + 2 * i + (lane >> 4);
            bmin_s[qb]  = mn;
            scale_s[qb] = scale;
        }
        // cell(x) = 256*(x - mn)/(scale + eps) = x*s1 + s2
        float s1 = __fdividef(256.0f, scale + EPSF);   // MUFU.RCP + FMUL
        float s2 = -mn * s1;
        const float* vi = reinterpret_cast<const float*>(&v);
        u32 w01 = 0, w23 = 0;
        #pragma unroll
        for (int j = 0; j < 4; j++) {
            float fcell = fmaf(vi[j], s1, s2);
            int ic = (int)fcell;        // trunc clamps tiny negatives to 0
            float2 L = lut[ic];         // ic can reach 256 -> 257 entries
            u32 h2 = __float_as_uint(L.y);
            u32 t16 = (fcell > L.x) ? (h2 >> 16) : (h2 & 0xffffu);
            if (j == 0) w01  = t16;
            if (j == 1) w01 |= t16 << 16;
            if (j == 2) w23  = t16;
            if (j == 3) w23 |= t16 << 16;
        }
        stash[2 * i]     = w01;
        stash[2 * i + 1] = w23;
    }
    __syncthreads();

    // ---- phase 2: row-level min/max of the 128 block scales ----
    if (warp == 0) {
        float a0 = scale_s[lane];
        float a1 = scale_s[lane + 32];
        float a2 = scale_s[lane + 64];
        float a3 = scale_s[lane + 96];
        float mn = fminf(fminf(a0, a1), fminf(a2, a3));
        float mx = fmaxf(fmaxf(a0, a1), fmaxf(a2, a3));
        #pragma unroll
        for (int o = 16; o >= 1; o >>= 1) {
            mn = fminf(mn, __shfl_xor_sync(0xffffffffu, mn, o));
            mx = fmaxf(mx, __shfl_xor_sync(0xffffffffu, mx, o));
        }
        if (lane == 0) { sm_smin = mn; sm_smax = mx; }
    }
    __syncthreads();

    // ---- phase 3: per-block output constants ----
    if (tid < NB) {
        float smin  = sm_smin, smax = sm_smax;
        float scale = scale_s[tid];
        float bmin  = bmin_s[tid];
        float d     = smax - smin;
        // double quantization of scale (8-bit, round-half-even = rintf)
        float sq    = rintf((scale - smin) / (d + EPSF) * 255.0f);
        float srec  = smin + sq / 255.0f * d;
        // out = (t+1)/2 * srec + bmin == t*a + b
        float a = srec * 0.5f;
        float b = a + bmin;
        qc[tid] = make_float2(a, b);
    }
    __syncthreads();

    // ---- phase 4: dequant from register stash, coalesced store ----
    #pragma unroll
    for (int i = 0; i < 8; i++) {
        int qb = qb_base + 2 * i + (lane >> 4);
        int e  = (qb_base + 2 * i) * BS + lane * 4;
        float2 ab = qc[qb];
        u32 w01 = stash[2 * i];
        u32 w23 = stash[2 * i + 1];
        __half2 h01 = *reinterpret_cast<__half2*>(&w01);
        __half2 h23 = *reinterpret_cast<__half2*>(&w23);
        float4 o;
        o.x = fmaf(__low2float(h01),  ab.x, ab.y);
        o.y = fmaf(__high2float(h01), ab.x, ab.y);
        o.z = fmaf(__low2float(h23),  ab.x, ab.y);
        o.w = fmaf(__high2float(h23), ab.x, ab.y);
        *reinterpret_cast<float4*>(out + row_base + e) = o;
    }
}

extern "C" void kernel_launch(void* const* d_in, const int* in_sizes, int n_in,
                              void* d_out, int out_size)
{
    const float* x = (const float*)d_in[0];
    float* out = (float*)d_out;
    int rows = in_sizes[0] / COLS;   // 2048
    nf4_kernel<<<rows, NTHREADS>>>(x, out);
}